// round 1
// baseline (speedup 1.0000x reference)
#include <cuda_runtime.h>

// ---------------------------------------------------------------------------
// Routing_2259152797848: capsule routing
//   x:[n,128] f32, W:[128,128] f32, b:[128] f32, neighbor_id:[n*32] int64|int32
//   out:[n,128] f32
// Pipeline:
//   k_detect : sniff neighbor_id element width (int64 vs jax-demoted int32)
//   k_zero   : zero padded row n of the normalized-feature table g_z
//   k_fc     : g_z[0..n) = caps_normalize(relu(x @ W^T + b))
//   k_route  : per-node block: gather 32 neighbor rows to SMEM, 3 routing iters
// ---------------------------------------------------------------------------

#define MAXN 50016
#define D    128
#define CH   8
#define KD   16
#define M    32

// normalized features + 1 zero row (padded neighbor id == n)
__device__ float g_z[(size_t)(MAXN + 1) * D];
__device__ int   g_is64;

// --- detect neighbor_id width ------------------------------------------------
// int64 little-endian with values in [0,n]: every odd 32-bit word is 0.
// int32 data: odd words are random ids, P(all zero) ~ (1/50001)^128 ~ 0.
__global__ void k_detect(const int* __restrict__ w) {
    if (threadIdx.x == 0) {
        int any = 0;
        #pragma unroll 8
        for (int i = 0; i < 128; i++) any |= w[2 * i + 1];
        g_is64 = (any == 0) ? 1 : 0;
    }
}

__global__ void k_zero(int n) {
    g_z[(size_t)n * D + threadIdx.x] = 0.0f;
}

// --- FC + relu + per-capsule normalize ---------------------------------------
// 128 threads, 32 rows per block. W^T tile in padded SMEM (132-float rows),
// 8x4 register blocking, float4 shared loads.
__global__ void k_fc(const float* __restrict__ x, const float* __restrict__ W,
                     const float* __restrict__ b, int n) {
    extern __shared__ float smem[];
    float* w_s = smem;             // [128][132] : w_s[j*132+k] = W[j*128+k]
    float* x_s = smem + 128 * 132; // [32][128]

    const int t = threadIdx.x;
    const int r0 = blockIdx.x * 32;

    // load W (4096 float4), padded rows of 33 float4
    const float4* W4 = (const float4*)W;
    float4* ws4 = (float4*)w_s;
    #pragma unroll
    for (int i = 0; i < 32; i++) {
        int idx4 = t + 128 * i;          // 0..4095
        int j = idx4 >> 5, kk = idx4 & 31;
        ws4[j * 33 + kk] = W4[idx4];
    }
    // load x tile (1024 float4), zero-fill past n
    const float4* X4 = (const float4*)x;
    float4* xs4 = (float4*)x_s;
    #pragma unroll
    for (int i = 0; i < 8; i++) {
        int idx4 = t + 128 * i;          // 0..1023
        int r = idx4 >> 5, kk = idx4 & 31;
        float4 v = make_float4(0.f, 0.f, 0.f, 0.f);
        if (r0 + r < n) v = X4[(size_t)(r0 + r) * 32 + kk];
        xs4[r * 32 + kk] = v;
    }
    __syncthreads();

    const int tx = t & 31;   // column lane
    const int ty = t >> 5;   // row group (0..3)

    float acc[8][4];
    #pragma unroll
    for (int rr = 0; rr < 8; rr++)
        #pragma unroll
        for (int cc = 0; cc < 4; cc++) acc[rr][cc] = 0.f;

    #pragma unroll 4
    for (int k4 = 0; k4 < 32; k4++) {
        float4 wv[4];
        #pragma unroll
        for (int cc = 0; cc < 4; cc++) wv[cc] = ws4[(tx + 32 * cc) * 33 + k4];
        float4 xr[8];
        #pragma unroll
        for (int rr = 0; rr < 8; rr++) xr[rr] = xs4[(ty + 4 * rr) * 32 + k4];
        #pragma unroll
        for (int rr = 0; rr < 8; rr++)
            #pragma unroll
            for (int cc = 0; cc < 4; cc++) {
                acc[rr][cc] = fmaf(xr[rr].x, wv[cc].x, acc[rr][cc]);
                acc[rr][cc] = fmaf(xr[rr].y, wv[cc].y, acc[rr][cc]);
                acc[rr][cc] = fmaf(xr[rr].z, wv[cc].z, acc[rr][cc]);
                acc[rr][cc] = fmaf(xr[rr].w, wv[cc].w, acc[rr][cc]);
            }
    }

    float bv[4];
    #pragma unroll
    for (int cc = 0; cc < 4; cc++) bv[cc] = b[tx + 32 * cc];

    // relu + bias, then L2-normalize within each 16-col channel.
    // Channel group == 16-lane shfl group (lanes 0-15 / 16-31 per cc).
    #pragma unroll
    for (int rr = 0; rr < 8; rr++) {
        int row = r0 + ty + 4 * rr;
        #pragma unroll
        for (int cc = 0; cc < 4; cc++) {
            float v = fmaxf(acc[rr][cc] + bv[cc], 0.f);
            float s = v * v;
            s += __shfl_xor_sync(0xffffffffu, s, 1);
            s += __shfl_xor_sync(0xffffffffu, s, 2);
            s += __shfl_xor_sync(0xffffffffu, s, 4);
            s += __shfl_xor_sync(0xffffffffu, s, 8);
            float inv = 1.0f / fmaxf(sqrtf(s), 1e-12f);
            if (row < n) g_z[(size_t)row * D + tx + 32 * cc] = v * inv;
        }
    }
}

// --- routing: one block (128 threads) per node --------------------------------
__global__ __launch_bounds__(128) void k_route(const void* __restrict__ nid_raw,
                                               float* __restrict__ out, int n) {
    __shared__ __align__(16) float nb[M * 132];  // 132-pad: (m + 4c) mod 32 bank-free
    __shared__ float ps[M * CH];
    __shared__ __align__(16) float us[D];
    __shared__ int ids[M];

    const int t = threadIdx.x;
    const int node = blockIdx.x;
    const int is64 = g_is64;

    if (t < M) {
        long long id;
        if (is64) id = ((const long long*)nid_raw)[(size_t)node * M + t];
        else      id = (long long)((const int*)nid_raw)[(size_t)node * M + t];
        ids[t] = (int)id;          // in [0, n]; row n is the zero row
    }
    const float xc = g_z[(size_t)node * D + t];  // x_caps element (c=t/16,k=t%16)
    us[t] = xc;
    __syncthreads();

    // gather 32 neighbor rows (512B each, coalesced) into padded SMEM
    const float4* Z4 = (const float4*)g_z;
    #pragma unroll
    for (int i = 0; i < 8; i++) {
        int idx4 = t + 128 * i;              // 0..1023
        int row = idx4 >> 5, off = idx4 & 31;
        float4 v = Z4[(size_t)ids[row] * 32 + off];
        *(float4*)&nb[row * 132 + off * 4] = v;
    }
    __syncthreads();

    const int cA = t & 7;      // phase A: thread = (m0, c)
    const int m0 = t >> 3;     // handles m0 and m0+16
    const int cB = t >> 4;     // phase B: thread = (c, k)
    const int kB = t & 15;
    const float4* nb4 = (const float4*)nb;
    const float4* us4 = (const float4*)us;

    for (int it = 0; it < 3; it++) {
        // ---- phase A: p[m,c] = softmax_c( <u[c,:], nb[m,c,:]> ) ----
        float4 u0 = us4[cA * 4 + 0], u1 = us4[cA * 4 + 1];
        float4 u2 = us4[cA * 4 + 2], u3 = us4[cA * 4 + 3];
        float d[2];
        #pragma unroll
        for (int h = 0; h < 2; h++) {
            int m = m0 + 16 * h;
            const float4* p4 = &nb4[m * 33 + cA * 4];
            float4 b0 = p4[0], b1 = p4[1], b2 = p4[2], b3 = p4[3];
            float s;
            s  = u0.x * b0.x + u0.y * b0.y + u0.z * b0.z + u0.w * b0.w;
            s += u1.x * b1.x + u1.y * b1.y + u1.z * b1.z + u1.w * b1.w;
            s += u2.x * b2.x + u2.y * b2.y + u2.z * b2.z + u2.w * b2.w;
            s += u3.x * b3.x + u3.y * b3.y + u3.z * b3.z + u3.w * b3.w;
            d[h] = s;
        }
        // softmax over c == 8 consecutive lanes (TAU = 1)
        #pragma unroll
        for (int h = 0; h < 2; h++) {
            float mx = d[h];
            mx = fmaxf(mx, __shfl_xor_sync(0xffffffffu, mx, 1));
            mx = fmaxf(mx, __shfl_xor_sync(0xffffffffu, mx, 2));
            mx = fmaxf(mx, __shfl_xor_sync(0xffffffffu, mx, 4));
            float e = __expf(d[h] - mx);
            float sm = e;
            sm += __shfl_xor_sync(0xffffffffu, sm, 1);
            sm += __shfl_xor_sync(0xffffffffu, sm, 2);
            sm += __shfl_xor_sync(0xffffffffu, sm, 4);
            ps[(m0 + 16 * h) * CH + cA] = __fdividef(e, sm);
        }
        __syncthreads();

        // ---- phase B: u[c,k] = x_caps + sum_m p[m,c]*nb[m,c,k] ----
        float acc = xc;
        #pragma unroll
        for (int mm = 0; mm < M; mm++)
            acc = fmaf(ps[mm * CH + cB], nb[mm * 132 + cB * 16 + kB], acc);

        if (it < 2) {
            float s2 = acc * acc;
            s2 += __shfl_xor_sync(0xffffffffu, s2, 1);
            s2 += __shfl_xor_sync(0xffffffffu, s2, 2);
            s2 += __shfl_xor_sync(0xffffffffu, s2, 4);
            s2 += __shfl_xor_sync(0xffffffffu, s2, 8);
            acc *= 1.0f / fmaxf(sqrtf(s2), 1e-12f);
            us[t] = acc;
            __syncthreads();
        } else {
            out[(size_t)node * D + t] = acc;
        }
    }
}

// ---------------------------------------------------------------------------
extern "C" void kernel_launch(void* const* d_in, const int* in_sizes, int n_in,
                              void* d_out, int out_size) {
    const float* x = (const float*)d_in[0];
    const float* W = (const float*)d_in[1];
    const float* b = (const float*)d_in[2];
    const void*  nid = d_in[3];
    float* out = (float*)d_out;

    int n = in_sizes[0] / D;

    static const size_t FC_SMEM = (size_t)(128 * 132 + 32 * 128) * sizeof(float);
    cudaFuncSetAttribute(k_fc, cudaFuncAttributeMaxDynamicSharedMemorySize,
                         (int)FC_SMEM);

    k_detect<<<1, 32>>>((const int*)nid);
    k_zero<<<1, D>>>(n);
    int nblk = (n + 31) / 32;
    k_fc<<<nblk, 128, FC_SMEM>>>(x, W, b, n);
    k_route<<<n, 128>>>(nid, out, n);
}

// round 2
// speedup vs baseline: 1.5329x; 1.5329x over previous
#include <cuda_runtime.h>

// ---------------------------------------------------------------------------
// Routing_2259152797848: capsule routing
//   x:[n,128] f32, W:[128,128] f32, b:[128] f32, neighbor_id:[n*32] int64|int32
//   out:[n,128] f32
// R2: register-resident neighbor tiles in k_route (L1 pipe was 95.7% busy).
// ---------------------------------------------------------------------------

#define MAXN 50016
#define D    128
#define CH   8
#define KD   16
#define M    32

// normalized features + 1 zero row (padded neighbor id == n)
__device__ float g_z[(size_t)(MAXN + 1) * D];
__device__ int   g_is64;

// --- detect neighbor_id width ------------------------------------------------
__global__ void k_detect(const int* __restrict__ w) {
    if (threadIdx.x == 0) {
        int any = 0;
        #pragma unroll 8
        for (int i = 0; i < 128; i++) any |= w[2 * i + 1];
        g_is64 = (any == 0) ? 1 : 0;
    }
}

__global__ void k_zero(int n) {
    g_z[(size_t)n * D + threadIdx.x] = 0.0f;
}

// --- FC + relu + per-capsule normalize ---------------------------------------
__global__ void k_fc(const float* __restrict__ x, const float* __restrict__ W,
                     const float* __restrict__ b, int n) {
    extern __shared__ float smem[];
    float* w_s = smem;             // [128][132]
    float* x_s = smem + 128 * 132; // [32][128]

    const int t = threadIdx.x;
    const int r0 = blockIdx.x * 32;

    const float4* W4 = (const float4*)W;
    float4* ws4 = (float4*)w_s;
    #pragma unroll
    for (int i = 0; i < 32; i++) {
        int idx4 = t + 128 * i;
        int j = idx4 >> 5, kk = idx4 & 31;
        ws4[j * 33 + kk] = W4[idx4];
    }
    const float4* X4 = (const float4*)x;
    float4* xs4 = (float4*)x_s;
    #pragma unroll
    for (int i = 0; i < 8; i++) {
        int idx4 = t + 128 * i;
        int r = idx4 >> 5, kk = idx4 & 31;
        float4 v = make_float4(0.f, 0.f, 0.f, 0.f);
        if (r0 + r < n) v = X4[(size_t)(r0 + r) * 32 + kk];
        xs4[r * 32 + kk] = v;
    }
    __syncthreads();

    const int tx = t & 31;
    const int ty = t >> 5;

    float acc[8][4];
    #pragma unroll
    for (int rr = 0; rr < 8; rr++)
        #pragma unroll
        for (int cc = 0; cc < 4; cc++) acc[rr][cc] = 0.f;

    #pragma unroll 4
    for (int k4 = 0; k4 < 32; k4++) {
        float4 wv[4];
        #pragma unroll
        for (int cc = 0; cc < 4; cc++) wv[cc] = ws4[(tx + 32 * cc) * 33 + k4];
        float4 xr[8];
        #pragma unroll
        for (int rr = 0; rr < 8; rr++) xr[rr] = xs4[(ty + 4 * rr) * 32 + k4];
        #pragma unroll
        for (int rr = 0; rr < 8; rr++)
            #pragma unroll
            for (int cc = 0; cc < 4; cc++) {
                acc[rr][cc] = fmaf(xr[rr].x, wv[cc].x, acc[rr][cc]);
                acc[rr][cc] = fmaf(xr[rr].y, wv[cc].y, acc[rr][cc]);
                acc[rr][cc] = fmaf(xr[rr].z, wv[cc].z, acc[rr][cc]);
                acc[rr][cc] = fmaf(xr[rr].w, wv[cc].w, acc[rr][cc]);
            }
    }

    float bv[4];
    #pragma unroll
    for (int cc = 0; cc < 4; cc++) bv[cc] = b[tx + 32 * cc];

    #pragma unroll
    for (int rr = 0; rr < 8; rr++) {
        int row = r0 + ty + 4 * rr;
        #pragma unroll
        for (int cc = 0; cc < 4; cc++) {
            float v = fmaxf(acc[rr][cc] + bv[cc], 0.f);
            float s = v * v;
            s += __shfl_xor_sync(0xffffffffu, s, 1);
            s += __shfl_xor_sync(0xffffffffu, s, 2);
            s += __shfl_xor_sync(0xffffffffu, s, 4);
            s += __shfl_xor_sync(0xffffffffu, s, 8);
            float inv = 1.0f / fmaxf(sqrtf(s), 1e-12f);
            if (row < n) g_z[(size_t)row * D + tx + 32 * cc] = v * inv;
        }
    }
}

__device__ __forceinline__ float dot4(float4 a, float4 b) {
    return a.x * b.x + a.y * b.y + a.z * b.z + a.w * b.w;
}

// --- routing: one block (128 threads) per node --------------------------------
// Register-resident neighbor tiles:
//   phase A: thread (m0 = t>>3, cA = t&7) keeps rows nb[m0][cA][:], nb[m0+16][cA][:]
//            as 8 float4 registers
//   phase B: thread (cB = t>>4, kB = t&15) keeps nb[m][cB][kB], m=0..31 (32 regs)
// Per-iteration SMEM traffic: 4 LDS.128 (u) + 2 STS (p) + 8 broadcast LDS.128 (p)
// + 1 STS (u).
__global__ __launch_bounds__(128) void k_route(const void* __restrict__ nid_raw,
                                               float* __restrict__ out, int n) {
    __shared__ __align__(16) float us[D];
    __shared__ __align__(16) float ps[CH * 36];   // ps[c*36 + m], 36-pad: conflict-free
    __shared__ int ids[M];

    const int t = threadIdx.x;
    const int node = blockIdx.x;
    const int is64 = g_is64;

    if (t < M) {
        long long id;
        if (is64) id = ((const long long*)nid_raw)[(size_t)node * M + t];
        else      id = (long long)((const int*)nid_raw)[(size_t)node * M + t];
        ids[t] = (int)id;          // in [0, n]; row n is the zero row
    }
    const float xc = g_z[(size_t)node * D + t];
    us[t] = xc;
    __syncthreads();

    const int m0 = t >> 3, cA = t & 7;   // phase-A identity
    const int cB = t >> 4;               // phase-B identity (kB implicit in t)

    // phase-A register tile: two capsule rows (16 floats each)
    const float4* Z4 = (const float4*)g_z;
    float4 a0[4], a1[4];
    {
        size_t r0 = (size_t)ids[m0] * 32 + (size_t)cA * 4;
        size_t r1 = (size_t)ids[m0 + 16] * 32 + (size_t)cA * 4;
        #pragma unroll
        for (int j = 0; j < 4; j++) { a0[j] = Z4[r0 + j]; a1[j] = Z4[r1 + j]; }
    }

    // phase-B register tile: one (c,k) element of each of the 32 neighbors
    float nbr[M];
    #pragma unroll
    for (int m = 0; m < M; m++)
        nbr[m] = g_z[(size_t)ids[m] * D + t];

    const float4* us4 = (const float4*)us;

    for (int it = 0; it < 3; it++) {
        // ---- phase A: d[m,c] = <u[c,:], nb[m,c,:]>, softmax over c (8 lanes)
        float4 u0 = us4[cA * 4 + 0], u1 = us4[cA * 4 + 1];
        float4 u2 = us4[cA * 4 + 2], u3 = us4[cA * 4 + 3];
        float d0 = dot4(u0, a0[0]) + dot4(u1, a0[1]) + dot4(u2, a0[2]) + dot4(u3, a0[3]);
        float d1 = dot4(u0, a1[0]) + dot4(u1, a1[1]) + dot4(u2, a1[2]) + dot4(u3, a1[3]);

        float mx0 = d0, mx1 = d1;
        mx0 = fmaxf(mx0, __shfl_xor_sync(0xffffffffu, mx0, 1));
        mx1 = fmaxf(mx1, __shfl_xor_sync(0xffffffffu, mx1, 1));
        mx0 = fmaxf(mx0, __shfl_xor_sync(0xffffffffu, mx0, 2));
        mx1 = fmaxf(mx1, __shfl_xor_sync(0xffffffffu, mx1, 2));
        mx0 = fmaxf(mx0, __shfl_xor_sync(0xffffffffu, mx0, 4));
        mx1 = fmaxf(mx1, __shfl_xor_sync(0xffffffffu, mx1, 4));
        float e0 = __expf(d0 - mx0);
        float e1 = __expf(d1 - mx1);
        float s0 = e0, s1 = e1;
        s0 += __shfl_xor_sync(0xffffffffu, s0, 1);
        s1 += __shfl_xor_sync(0xffffffffu, s1, 1);
        s0 += __shfl_xor_sync(0xffffffffu, s0, 2);
        s1 += __shfl_xor_sync(0xffffffffu, s1, 2);
        s0 += __shfl_xor_sync(0xffffffffu, s0, 4);
        s1 += __shfl_xor_sync(0xffffffffu, s1, 4);
        ps[cA * 36 + m0]      = __fdividef(e0, s0);
        ps[cA * 36 + m0 + 16] = __fdividef(e1, s1);
        __syncthreads();

        // ---- phase B: u[c,k] = x_caps + sum_m p[m,c]*nb[m,c,k]
        float acc = xc;
        #pragma unroll
        for (int j = 0; j < 8; j++) {
            float4 p = *(const float4*)&ps[cB * 36 + 4 * j];
            acc = fmaf(p.x, nbr[4 * j + 0], acc);
            acc = fmaf(p.y, nbr[4 * j + 1], acc);
            acc = fmaf(p.z, nbr[4 * j + 2], acc);
            acc = fmaf(p.w, nbr[4 * j + 3], acc);
        }

        if (it < 2) {
            float s2 = acc * acc;
            s2 += __shfl_xor_sync(0xffffffffu, s2, 1);
            s2 += __shfl_xor_sync(0xffffffffu, s2, 2);
            s2 += __shfl_xor_sync(0xffffffffu, s2, 4);
            s2 += __shfl_xor_sync(0xffffffffu, s2, 8);
            acc *= 1.0f / fmaxf(sqrtf(s2), 1e-12f);
            us[t] = acc;
            __syncthreads();
        } else {
            out[(size_t)node * D + t] = acc;
        }
    }
}

// ---------------------------------------------------------------------------
extern "C" void kernel_launch(void* const* d_in, const int* in_sizes, int n_in,
                              void* d_out, int out_size) {
    const float* x = (const float*)d_in[0];
    const float* W = (const float*)d_in[1];
    const float* b = (const float*)d_in[2];
    const void*  nid = d_in[3];
    float* out = (float*)d_out;

    int n = in_sizes[0] / D;

    static const size_t FC_SMEM = (size_t)(128 * 132 + 32 * 128) * sizeof(float);
    cudaFuncSetAttribute(k_fc, cudaFuncAttributeMaxDynamicSharedMemorySize,
                         (int)FC_SMEM);

    k_detect<<<1, 32>>>((const int*)nid);
    k_zero<<<1, D>>>(n);
    int nblk = (n + 31) / 32;
    k_fc<<<nblk, 128, FC_SMEM>>>(x, W, b, n);
    k_route<<<n, 128>>>(nid, out, n);
}

// round 3
// speedup vs baseline: 2.3011x; 1.5011x over previous
#include <cuda_runtime.h>

// ---------------------------------------------------------------------------
// Routing_2259152797848: capsule routing
//   x:[n,128] f32, W:[128,128] f32, b:[128] f32, neighbor_id:[n*32] int64|int32
//   out:[n,128] f32
// R3: single register-resident gather; phase-A dots via split-tree shuffle
//     reduction in the phase-B layout (kills the duplicate LDG tile + us[]).
// ---------------------------------------------------------------------------

#define MAXN 50016
#define D    128
#define CH   8
#define KD   16
#define M    32

__device__ float g_z[(size_t)(MAXN + 1) * D];
__device__ int   g_is64;

__global__ void k_detect(const int* __restrict__ w) {
    if (threadIdx.x == 0) {
        int any = 0;
        #pragma unroll 8
        for (int i = 0; i < 128; i++) any |= w[2 * i + 1];
        g_is64 = (any == 0) ? 1 : 0;
    }
}

__global__ void k_zero(int n) {
    g_z[(size_t)n * D + threadIdx.x] = 0.0f;
}

// --- FC + relu + per-capsule normalize ---------------------------------------
__global__ void k_fc(const float* __restrict__ x, const float* __restrict__ W,
                     const float* __restrict__ b, int n) {
    extern __shared__ float smem[];
    float* w_s = smem;             // [128][132]
    float* x_s = smem + 128 * 132; // [32][128]

    const int t = threadIdx.x;
    const int r0 = blockIdx.x * 32;

    const float4* W4 = (const float4*)W;
    float4* ws4 = (float4*)w_s;
    #pragma unroll
    for (int i = 0; i < 32; i++) {
        int idx4 = t + 128 * i;
        int j = idx4 >> 5, kk = idx4 & 31;
        ws4[j * 33 + kk] = W4[idx4];
    }
    const float4* X4 = (const float4*)x;
    float4* xs4 = (float4*)x_s;
    #pragma unroll
    for (int i = 0; i < 8; i++) {
        int idx4 = t + 128 * i;
        int r = idx4 >> 5, kk = idx4 & 31;
        float4 v = make_float4(0.f, 0.f, 0.f, 0.f);
        if (r0 + r < n) v = X4[(size_t)(r0 + r) * 32 + kk];
        xs4[r * 32 + kk] = v;
    }
    __syncthreads();

    const int tx = t & 31;
    const int ty = t >> 5;

    float acc[8][4];
    #pragma unroll
    for (int rr = 0; rr < 8; rr++)
        #pragma unroll
        for (int cc = 0; cc < 4; cc++) acc[rr][cc] = 0.f;

    #pragma unroll 4
    for (int k4 = 0; k4 < 32; k4++) {
        float4 wv[4];
        #pragma unroll
        for (int cc = 0; cc < 4; cc++) wv[cc] = ws4[(tx + 32 * cc) * 33 + k4];
        float4 xr[8];
        #pragma unroll
        for (int rr = 0; rr < 8; rr++) xr[rr] = xs4[(ty + 4 * rr) * 32 + k4];
        #pragma unroll
        for (int rr = 0; rr < 8; rr++)
            #pragma unroll
            for (int cc = 0; cc < 4; cc++) {
                acc[rr][cc] = fmaf(xr[rr].x, wv[cc].x, acc[rr][cc]);
                acc[rr][cc] = fmaf(xr[rr].y, wv[cc].y, acc[rr][cc]);
                acc[rr][cc] = fmaf(xr[rr].z, wv[cc].z, acc[rr][cc]);
                acc[rr][cc] = fmaf(xr[rr].w, wv[cc].w, acc[rr][cc]);
            }
    }

    float bv[4];
    #pragma unroll
    for (int cc = 0; cc < 4; cc++) bv[cc] = b[tx + 32 * cc];

    #pragma unroll
    for (int rr = 0; rr < 8; rr++) {
        int row = r0 + ty + 4 * rr;
        #pragma unroll
        for (int cc = 0; cc < 4; cc++) {
            float v = fmaxf(acc[rr][cc] + bv[cc], 0.f);
            float s = v * v;
            s += __shfl_xor_sync(0xffffffffu, s, 1);
            s += __shfl_xor_sync(0xffffffffu, s, 2);
            s += __shfl_xor_sync(0xffffffffu, s, 4);
            s += __shfl_xor_sync(0xffffffffu, s, 8);
            float inv = 1.0f / fmaxf(sqrtf(s), 1e-12f);
            if (row < n) g_z[(size_t)row * D + tx + 32 * cc] = v * inv;
        }
    }
}

// --- routing: one block (128 threads) per node --------------------------------
// Single gather: thread t=(c= t>>4, k= t&15) holds nb[m][c][k] for m=0..31.
// d[m,c] = sum_k u[c,k]*nb[m,c,k]: split-tree shuffle reduction over the
// 16 k-lanes (30 shfl), finishing with 2 dots per lane -> SMEM d_s[m][c].
// Softmax over c via 8-lane shfl in (m0,cA) layout, p -> SMEM, phase B in regs.
__global__ __launch_bounds__(128) void k_route(const void* __restrict__ nid_raw,
                                               float* __restrict__ out, int n) {
    __shared__ float d_s[M * 9];        // d_s[m*9+c]; stride 9: bijective mod 32
    __shared__ __align__(16) float ps[CH * 36];  // ps[c*36+m]
    __shared__ int ids[M];

    const int t = threadIdx.x;
    const int node = blockIdx.x;
    const int is64 = g_is64;

    if (t < M) {
        long long id;
        if (is64) id = ((const long long*)nid_raw)[(size_t)node * M + t];
        else      id = (long long)((const int*)nid_raw)[(size_t)node * M + t];
        ids[t] = (int)id;
    }
    const float xc = g_z[(size_t)node * D + t];
    __syncthreads();

    // one gather: coalesced 128B per warp per m
    float nbr[M];
    #pragma unroll
    for (int m = 0; m < M; m++)
        nbr[m] = g_z[(size_t)ids[m] * D + t];

    const int cB = t >> 4;          // channel of this thread (phase B / tree)
    const int g  = t & 15;          // lane within 16-lane channel group
    const int m0 = t >> 3;          // softmax identity
    const int cA = t & 7;
    // m index owned after the tree: bit g0->+16, g1->+8, g2->+4, g3->+2
    const int mbase = ((g & 1) << 4) | ((g & 2) << 2) | (g & 4) | ((g >> 3) << 1);

    float u_val = xc;               // u[c,k] for this thread
    float acc;

    for (int it = 0; it < 3; it++) {
        // ---- tree reduction: d[m] = sum over 16 lanes of u_val*nbr[m] ----
        float s1[16];
        #pragma unroll
        for (int i = 0; i < 16; i++) {
            float lo = u_val * nbr[i];
            float hi = u_val * nbr[i + 16];
            float keep = (g & 1) ? hi : lo;
            float send = (g & 1) ? lo : hi;
            s1[i] = keep + __shfl_xor_sync(0xffffffffu, send, 1);
        }
        float s2[8];
        #pragma unroll
        for (int i = 0; i < 8; i++) {
            float keep = (g & 2) ? s1[i + 8] : s1[i];
            float send = (g & 2) ? s1[i] : s1[i + 8];
            s2[i] = keep + __shfl_xor_sync(0xffffffffu, send, 2);
        }
        float s3[4];
        #pragma unroll
        for (int i = 0; i < 4; i++) {
            float keep = (g & 4) ? s2[i + 4] : s2[i];
            float send = (g & 4) ? s2[i] : s2[i + 4];
            s3[i] = keep + __shfl_xor_sync(0xffffffffu, send, 4);
        }
        float s4[2];
        #pragma unroll
        for (int i = 0; i < 2; i++) {
            float keep = (g & 8) ? s3[i + 2] : s3[i];
            float send = (g & 8) ? s3[i] : s3[i + 2];
            s4[i] = keep + __shfl_xor_sync(0xffffffffu, send, 8);
        }
        d_s[(mbase + 0) * 9 + cB] = s4[0];
        d_s[(mbase + 1) * 9 + cB] = s4[1];
        __syncthreads();

        // ---- softmax over c (8 adjacent lanes), thread = (m0, cA) ----
        float d0 = d_s[m0 * 9 + cA];
        float d1 = d_s[(m0 + 16) * 9 + cA];
        float mx0 = d0, mx1 = d1;
        mx0 = fmaxf(mx0, __shfl_xor_sync(0xffffffffu, mx0, 1));
        mx1 = fmaxf(mx1, __shfl_xor_sync(0xffffffffu, mx1, 1));
        mx0 = fmaxf(mx0, __shfl_xor_sync(0xffffffffu, mx0, 2));
        mx1 = fmaxf(mx1, __shfl_xor_sync(0xffffffffu, mx1, 2));
        mx0 = fmaxf(mx0, __shfl_xor_sync(0xffffffffu, mx0, 4));
        mx1 = fmaxf(mx1, __shfl_xor_sync(0xffffffffu, mx1, 4));
        float e0 = __expf(d0 - mx0);
        float e1 = __expf(d1 - mx1);
        float sm0 = e0, sm1 = e1;
        sm0 += __shfl_xor_sync(0xffffffffu, sm0, 1);
        sm1 += __shfl_xor_sync(0xffffffffu, sm1, 1);
        sm0 += __shfl_xor_sync(0xffffffffu, sm0, 2);
        sm1 += __shfl_xor_sync(0xffffffffu, sm1, 2);
        sm0 += __shfl_xor_sync(0xffffffffu, sm0, 4);
        sm1 += __shfl_xor_sync(0xffffffffu, sm1, 4);
        ps[cA * 36 + m0]      = __fdividef(e0, sm0);
        ps[cA * 36 + m0 + 16] = __fdividef(e1, sm1);
        __syncthreads();

        // ---- phase B: u[c,k] = x_caps + sum_m p[m,c]*nb[m,c,k] ----
        acc = xc;
        #pragma unroll
        for (int j = 0; j < 8; j++) {
            float4 p = *(const float4*)&ps[cB * 36 + 4 * j];
            acc = fmaf(p.x, nbr[4 * j + 0], acc);
            acc = fmaf(p.y, nbr[4 * j + 1], acc);
            acc = fmaf(p.z, nbr[4 * j + 2], acc);
            acc = fmaf(p.w, nbr[4 * j + 3], acc);
        }

        if (it < 2) {
            float sq = acc * acc;
            sq += __shfl_xor_sync(0xffffffffu, sq, 1);
            sq += __shfl_xor_sync(0xffffffffu, sq, 2);
            sq += __shfl_xor_sync(0xffffffffu, sq, 4);
            sq += __shfl_xor_sync(0xffffffffu, sq, 8);
            u_val = acc * (1.0f / fmaxf(sqrtf(sq), 1e-12f));
        } else {
            out[(size_t)node * D + t] = acc;
        }
    }
}

// ---------------------------------------------------------------------------
extern "C" void kernel_launch(void* const* d_in, const int* in_sizes, int n_in,
                              void* d_out, int out_size) {
    const float* x = (const float*)d_in[0];
    const float* W = (const float*)d_in[1];
    const float* b = (const float*)d_in[2];
    const void*  nid = d_in[3];
    float* out = (float*)d_out;

    int n = in_sizes[0] / D;

    static const size_t FC_SMEM = (size_t)(128 * 132 + 32 * 128) * sizeof(float);
    cudaFuncSetAttribute(k_fc, cudaFuncAttributeMaxDynamicSharedMemorySize,
                         (int)FC_SMEM);

    k_detect<<<1, 32>>>((const int*)nid);
    k_zero<<<1, D>>>(n);
    int nblk = (n + 31) / 32;
    k_fc<<<nblk, 128, FC_SMEM>>>(x, W, b, n);
    k_route<<<n, 128>>>(nid, out, n);
}

// round 4
// speedup vs baseline: 2.5125x; 1.0919x over previous
#include <cuda_runtime.h>

// ---------------------------------------------------------------------------
// Routing_2259152797848: capsule routing
// R4: no-max softmax (|d|<=1 by normalization), rsqrt normalize,
//     2 nodes / 256-thread block with per-node named barriers.
// ---------------------------------------------------------------------------

#define MAXN 50016
#define D    128
#define CH   8
#define KD   16
#define M    32

__device__ float g_z[(size_t)(MAXN + 1) * D];
__device__ int   g_is64;

__global__ void k_detect(const int* __restrict__ w) {
    if (threadIdx.x == 0) {
        int any = 0;
        #pragma unroll 8
        for (int i = 0; i < 128; i++) any |= w[2 * i + 1];
        g_is64 = (any == 0) ? 1 : 0;
    }
}

__global__ void k_zero(int n) {
    g_z[(size_t)n * D + threadIdx.x] = 0.0f;
}

// --- FC + relu + per-capsule normalize ---------------------------------------
__global__ void k_fc(const float* __restrict__ x, const float* __restrict__ W,
                     const float* __restrict__ b, int n) {
    extern __shared__ float smem[];
    float* w_s = smem;             // [128][132]
    float* x_s = smem + 128 * 132; // [32][128]

    const int t = threadIdx.x;
    const int r0 = blockIdx.x * 32;

    const float4* W4 = (const float4*)W;
    float4* ws4 = (float4*)w_s;
    #pragma unroll
    for (int i = 0; i < 32; i++) {
        int idx4 = t + 128 * i;
        int j = idx4 >> 5, kk = idx4 & 31;
        ws4[j * 33 + kk] = W4[idx4];
    }
    const float4* X4 = (const float4*)x;
    float4* xs4 = (float4*)x_s;
    #pragma unroll
    for (int i = 0; i < 8; i++) {
        int idx4 = t + 128 * i;
        int r = idx4 >> 5, kk = idx4 & 31;
        float4 v = make_float4(0.f, 0.f, 0.f, 0.f);
        if (r0 + r < n) v = X4[(size_t)(r0 + r) * 32 + kk];
        xs4[r * 32 + kk] = v;
    }
    __syncthreads();

    const int tx = t & 31;
    const int ty = t >> 5;

    float acc[8][4];
    #pragma unroll
    for (int rr = 0; rr < 8; rr++)
        #pragma unroll
        for (int cc = 0; cc < 4; cc++) acc[rr][cc] = 0.f;

    #pragma unroll 4
    for (int k4 = 0; k4 < 32; k4++) {
        float4 wv[4];
        #pragma unroll
        for (int cc = 0; cc < 4; cc++) wv[cc] = ws4[(tx + 32 * cc) * 33 + k4];
        float4 xr[8];
        #pragma unroll
        for (int rr = 0; rr < 8; rr++) xr[rr] = xs4[(ty + 4 * rr) * 32 + k4];
        #pragma unroll
        for (int rr = 0; rr < 8; rr++)
            #pragma unroll
            for (int cc = 0; cc < 4; cc++) {
                acc[rr][cc] = fmaf(xr[rr].x, wv[cc].x, acc[rr][cc]);
                acc[rr][cc] = fmaf(xr[rr].y, wv[cc].y, acc[rr][cc]);
                acc[rr][cc] = fmaf(xr[rr].z, wv[cc].z, acc[rr][cc]);
                acc[rr][cc] = fmaf(xr[rr].w, wv[cc].w, acc[rr][cc]);
            }
    }

    float bv[4];
    #pragma unroll
    for (int cc = 0; cc < 4; cc++) bv[cc] = b[tx + 32 * cc];

    #pragma unroll
    for (int rr = 0; rr < 8; rr++) {
        int row = r0 + ty + 4 * rr;
        #pragma unroll
        for (int cc = 0; cc < 4; cc++) {
            float v = fmaxf(acc[rr][cc] + bv[cc], 0.f);
            float s = v * v;
            s += __shfl_xor_sync(0xffffffffu, s, 1);
            s += __shfl_xor_sync(0xffffffffu, s, 2);
            s += __shfl_xor_sync(0xffffffffu, s, 4);
            s += __shfl_xor_sync(0xffffffffu, s, 8);
            // 1/max(sqrt(s),1e-12) == rsqrt(max(s,1e-24))
            float inv = rsqrtf(fmaxf(s, 1e-24f));
            if (row < n) g_z[(size_t)row * D + tx + 32 * cc] = v * inv;
        }
    }
}

// --- routing: 256 threads = 2 independent nodes (128 threads each) -----------
__global__ __launch_bounds__(256) void k_route(const void* __restrict__ nid_raw,
                                               float* __restrict__ out, int n) {
    __shared__ float d_s[2][M * 9];          // d_s[grp][m*9+c]
    __shared__ __align__(16) float ps[2][CH * 36];  // ps[grp][c*36+m]
    __shared__ int ids[2][M];

    const int t   = threadIdx.x;
    const int grp = t >> 7;                  // node group 0/1
    const int tl  = t & 127;
    const int bid = 1 + grp;                 // named barrier id (warp-uniform)
    const int node = blockIdx.x * 2 + grp;
    if (node >= n) return;                   // whole 128-group exits together
    const int is64 = g_is64;

    if (tl < M) {
        long long id;
        if (is64) id = ((const long long*)nid_raw)[(size_t)node * M + tl];
        else      id = (long long)((const int*)nid_raw)[(size_t)node * M + tl];
        ids[grp][tl] = (int)id;
    }
    const float xc = g_z[(size_t)node * D + tl];
    asm volatile("bar.sync %0, %1;" :: "r"(bid), "r"(128) : "memory");

    // coalesced gather: one (c,k) column of all 32 neighbor rows
    float nbr[M];
    #pragma unroll
    for (int m = 0; m < M; m++)
        nbr[m] = g_z[(size_t)ids[grp][m] * D + tl];

    const int cB = tl >> 4;          // channel (tree / phase B)
    const int g  = tl & 15;          // lane within 16-lane channel group
    const int m0 = tl >> 3;          // softmax identity
    const int cA = tl & 7;
    const int mbase = ((g & 1) << 4) | ((g & 2) << 2) | (g & 4) | ((g >> 3) << 1);

    float u_val = xc;
    float acc;

    for (int it = 0; it < 3; it++) {
        // ---- tree: d[m] = sum_k u[c,k]*nb[m,c,k], split over 16 lanes ----
        float s1[16];
        #pragma unroll
        for (int i = 0; i < 16; i++) {
            float lo = u_val * nbr[i];
            float hi = u_val * nbr[i + 16];
            float keep = (g & 1) ? hi : lo;
            float send = (g & 1) ? lo : hi;
            s1[i] = keep + __shfl_xor_sync(0xffffffffu, send, 1);
        }
        float s2[8];
        #pragma unroll
        for (int i = 0; i < 8; i++) {
            float keep = (g & 2) ? s1[i + 8] : s1[i];
            float send = (g & 2) ? s1[i] : s1[i + 8];
            s2[i] = keep + __shfl_xor_sync(0xffffffffu, send, 2);
        }
        float s3[4];
        #pragma unroll
        for (int i = 0; i < 4; i++) {
            float keep = (g & 4) ? s2[i + 4] : s2[i];
            float send = (g & 4) ? s2[i] : s2[i + 4];
            s3[i] = keep + __shfl_xor_sync(0xffffffffu, send, 4);
        }
        float s4[2];
        #pragma unroll
        for (int i = 0; i < 2; i++) {
            float keep = (g & 8) ? s3[i + 2] : s3[i];
            float send = (g & 8) ? s3[i] : s3[i + 2];
            s4[i] = keep + __shfl_xor_sync(0xffffffffu, send, 8);
        }
        // |d| <= 1 (u, nb unit-normalized per capsule): exp safe without max
        d_s[grp][(mbase + 0) * 9 + cB] = __expf(s4[0]);
        d_s[grp][(mbase + 1) * 9 + cB] = __expf(s4[1]);
        asm volatile("bar.sync %0, %1;" :: "r"(bid), "r"(128) : "memory");

        // ---- softmax over c (8 adjacent lanes), thread = (m0, cA) ----
        float e0 = d_s[grp][m0 * 9 + cA];
        float e1 = d_s[grp][(m0 + 16) * 9 + cA];
        float sm0 = e0, sm1 = e1;
        sm0 += __shfl_xor_sync(0xffffffffu, sm0, 1);
        sm1 += __shfl_xor_sync(0xffffffffu, sm1, 1);
        sm0 += __shfl_xor_sync(0xffffffffu, sm0, 2);
        sm1 += __shfl_xor_sync(0xffffffffu, sm1, 2);
        sm0 += __shfl_xor_sync(0xffffffffu, sm0, 4);
        sm1 += __shfl_xor_sync(0xffffffffu, sm1, 4);
        ps[grp][cA * 36 + m0]      = __fdividef(e0, sm0);
        ps[grp][cA * 36 + m0 + 16] = __fdividef(e1, sm1);
        asm volatile("bar.sync %0, %1;" :: "r"(bid), "r"(128) : "memory");

        // ---- phase B: u[c,k] = x_caps + sum_m p[m,c]*nb[m,c,k] ----
        acc = xc;
        #pragma unroll
        for (int j = 0; j < 8; j++) {
            float4 p = *(const float4*)&ps[grp][cB * 36 + 4 * j];
            acc = fmaf(p.x, nbr[4 * j + 0], acc);
            acc = fmaf(p.y, nbr[4 * j + 1], acc);
            acc = fmaf(p.z, nbr[4 * j + 2], acc);
            acc = fmaf(p.w, nbr[4 * j + 3], acc);
        }

        if (it < 2) {
            float sq = acc * acc;
            sq += __shfl_xor_sync(0xffffffffu, sq, 1);
            sq += __shfl_xor_sync(0xffffffffu, sq, 2);
            sq += __shfl_xor_sync(0xffffffffu, sq, 4);
            sq += __shfl_xor_sync(0xffffffffu, sq, 8);
            u_val = acc * rsqrtf(fmaxf(sq, 1e-24f));
        } else {
            out[(size_t)node * D + tl] = acc;
        }
    }
}

// ---------------------------------------------------------------------------
extern "C" void kernel_launch(void* const* d_in, const int* in_sizes, int n_in,
                              void* d_out, int out_size) {
    const float* x = (const float*)d_in[0];
    const float* W = (const float*)d_in[1];
    const float* b = (const float*)d_in[2];
    const void*  nid = d_in[3];
    float* out = (float*)d_out;

    int n = in_sizes[0] / D;

    static const size_t FC_SMEM = (size_t)(128 * 132 + 32 * 128) * sizeof(float);
    cudaFuncSetAttribute(k_fc, cudaFuncAttributeMaxDynamicSharedMemorySize,
                         (int)FC_SMEM);

    k_detect<<<1, 32>>>((const int*)nid);
    k_zero<<<1, D>>>(n);
    int nblk = (n + 31) / 32;
    k_fc<<<nblk, 128, FC_SMEM>>>(x, W, b, n);
    k_route<<<(n + 1) / 2, 256>>>(nid, out, n);
}